// round 3
// baseline (speedup 1.0000x reference)
#include <cuda_runtime.h>
#include <cuda_bf16.h>
#include <cstdint>

// BasicEdgeModel: out[e] = relu(concat(x[src[e]], x[tgt[e]], ea[e]) @ W1 + b1) @ W2 + b2
// E=1,600,000  NODE_DIM=64  EDGE_DIM=32  K_IN=160  HID=128  OUT=64
//
// Round 2: fp32 baseline, packed f32x2 FMA (2 edges per instruction).
// FIX vs round 0/1: edge_index is int32 (JAX silently downgrades int64 with
// x64 disabled) — reading it as int64 produced garbage indices -> illegal access.
// Block = 128 threads handles TILE_E=16 edges.

#define E_TOTAL   1600000
#define TILE_E    16
#define K_IN      160
#define HID       128
#define OUTD      64
#define MSTRIDE   20     // padded row stride (floats): 8B-aligned rows, fewer bank conflicts

__device__ __forceinline__ unsigned long long pack2(float x) {
    unsigned long long r;
    asm("mov.b64 %0, {%1, %1};" : "=l"(r) : "f"(x));
    return r;
}
__device__ __forceinline__ unsigned long long ffma2(unsigned long long a,
                                                    unsigned long long b,
                                                    unsigned long long c) {
    unsigned long long d;
    asm("fma.rn.f32x2 %0, %1, %2, %3;" : "=l"(d) : "l"(a), "l"(b), "l"(c));
    return d;
}
__device__ __forceinline__ void unpack2(unsigned long long v, float& lo, float& hi) {
    asm("mov.b64 {%0, %1}, %2;" : "=f"(lo), "=f"(hi) : "l"(v));
}

__global__ void __launch_bounds__(128, 6)
edge_mlp_kernel(const float* __restrict__ x,
                const float* __restrict__ ea,
                const float* __restrict__ W1,
                const float* __restrict__ b1,
                const float* __restrict__ W2,
                const float* __restrict__ b2,
                const int* __restrict__ eidx,     // int32! [2, E] row-major
                float* __restrict__ out)
{
    __shared__ float merged[K_IN * MSTRIDE];   // [k][e] k-major, padded
    __shared__ float hbuf[HID * MSTRIDE];      // [j][e] padded
    __shared__ int   sidx[TILE_E];
    __shared__ int   tidx[TILE_E];

    const int t = threadIdx.x;
    const long long ebase = (long long)blockIdx.x * TILE_E;

    // ---- load the 16 src/tgt indices ----
    if (t < 32) {
        int e = t & 15;
        int row = t >> 4;                      // 0 = src, 1 = tgt
        int v = eidx[(long long)row * E_TOTAL + ebase + e];
        if (row == 0) sidx[e] = v;
        else          tidx[e] = v;
    }
    __syncthreads();

    // ---- phase 0: gather merged[160][16] = [x[src] | x[tgt] | ea] ----
    // 2560 floats = 640 float4; 128 threads x 5 float4 each.
    // Per edge: 40 float4 = 16 (src) + 16 (tgt) + 8 (edge_attr).
    #pragma unroll
    for (int r = 0; r < 5; r++) {
        int f = t + r * 128;            // 0..639
        int e = f / 40;
        int q = f - e * 40;
        const float4* src;
        if (q < 16)      src = (const float4*)(x + (long long)sidx[e] * 64) + q;
        else if (q < 32) src = (const float4*)(x + (long long)tidx[e] * 64) + (q - 16);
        else             src = (const float4*)(ea + (ebase + e) * 32) + (q - 32);
        float4 v = *src;
        int k = q * 4;
        merged[(k + 0) * MSTRIDE + e] = v.x;
        merged[(k + 1) * MSTRIDE + e] = v.y;
        merged[(k + 2) * MSTRIDE + e] = v.z;
        merged[(k + 3) * MSTRIDE + e] = v.w;
    }
    __syncthreads();

    // ---- phase 1: h[j][e] = relu(b1[j] + sum_k merged[k][e] * W1[k][j]) ----
    // thread j = t computes hidden unit j for all 16 edges (8 f32x2 accumulators).
    {
        unsigned long long acc[8];
        const unsigned long long binit = pack2(b1[t]);
        #pragma unroll
        for (int u = 0; u < 8; u++) acc[u] = binit;

        #pragma unroll 4
        for (int k = 0; k < K_IN; k++) {
            const unsigned long long w = pack2(W1[k * HID + t]);   // coalesced, L2-resident
            const unsigned long long* m =
                (const unsigned long long*)&merged[k * MSTRIDE];    // warp-broadcast LDS
            #pragma unroll
            for (int u = 0; u < 8; u++) acc[u] = ffma2(m[u], w, acc[u]);
        }

        #pragma unroll
        for (int u = 0; u < 8; u++) {
            float lo, hi;
            unpack2(acc[u], lo, hi);
            hbuf[t * MSTRIDE + 2 * u]     = fmaxf(lo, 0.0f);
            hbuf[t * MSTRIDE + 2 * u + 1] = fmaxf(hi, 0.0f);
        }
    }
    __syncthreads();

    // ---- phase 2: out[e][n] = b2[n] + sum_j h[j][e] * W2[j][n] ----
    // thread t: n = t&63, edge group g = t>>6 covers edges g*8 .. g*8+7.
    {
        const int n = t & 63;
        const int g = t >> 6;
        unsigned long long acc[4];
        const unsigned long long binit = pack2(b2[n]);
        #pragma unroll
        for (int u = 0; u < 4; u++) acc[u] = binit;

        #pragma unroll 4
        for (int j = 0; j < HID; j++) {
            const unsigned long long w = pack2(W2[j * OUTD + n]);   // coalesced / broadcast
            const unsigned long long* m =
                (const unsigned long long*)&hbuf[j * MSTRIDE + g * 8];
            #pragma unroll
            for (int u = 0; u < 4; u++) acc[u] = ffma2(m[u], w, acc[u]);
        }

        float* o = out + (ebase + g * 8) * OUTD + n;
        #pragma unroll
        for (int u = 0; u < 4; u++) {
            float lo, hi;
            unpack2(acc[u], lo, hi);
            o[(2 * u) * OUTD]     = lo;   // 256B-coalesced rows across the 64 n-lanes
            o[(2 * u + 1) * OUTD] = hi;
        }
    }
}

extern "C" void kernel_launch(void* const* d_in, const int* in_sizes, int n_in,
                              void* d_out, int out_size) {
    const float* x   = (const float*)d_in[0];
    const float* ea  = (const float*)d_in[1];
    const float* W1  = (const float*)d_in[2];
    const float* b1  = (const float*)d_in[3];
    const float* W2  = (const float*)d_in[4];
    const float* b2  = (const float*)d_in[5];
    const int*   ei  = (const int*)d_in[6];
    float*       out = (float*)d_out;

    const int n_blocks = E_TOTAL / TILE_E;   // 100,000
    edge_mlp_kernel<<<n_blocks, 128>>>(x, ea, W1, b1, W2, b2, ei, out);
}

// round 5
// speedup vs baseline: 2.6742x; 2.6742x over previous
#include <cuda_runtime.h>
#include <cuda_bf16.h>
#include <cstdint>

// BasicEdgeModel restructured:
//   Pa = x @ W1[0:64]    (precomputed per launch, 100K x 128)
//   Pb = x @ W1[64:128]  (precomputed per launch)
//   h  = relu(Pa[src] + Pb[tgt] + ea @ W1[128:160] + b1)
//   out= h @ W2 + b2
// MACs drop 4.59e10 -> 1.97e10. Register-tiled f32x2 FMA, weights via L1 LDG.

#define E_TOTAL   1600000
#define N_NODES   100000
#define NODE_DIM  64
#define EDGE_DIM  32
#define HID       128
#define OUTD      64
#define TILE_E    32

typedef unsigned long long ull;

__device__ float g_Pa[(size_t)N_NODES * HID];   // 51.2 MB
__device__ float g_Pb[(size_t)N_NODES * HID];   // 51.2 MB

__device__ __forceinline__ ull pack2(float x) {
    ull r; asm("mov.b64 %0, {%1, %1};" : "=l"(r) : "f"(x)); return r;
}
__device__ __forceinline__ ull pack2f(float lo, float hi) {
    ull r; asm("mov.b64 %0, {%1, %2};" : "=l"(r) : "f"(lo), "f"(hi)); return r;
}
__device__ __forceinline__ ull ffma2(ull a, ull b, ull c) {
    ull d; asm("fma.rn.f32x2 %0, %1, %2, %3;" : "=l"(d) : "l"(a), "l"(b), "l"(c)); return d;
}
__device__ __forceinline__ void unpack2(ull v, float& lo, float& hi) {
    asm("mov.b64 {%0, %1}, %2;" : "=f"(lo), "=f"(hi) : "l"(v));
}

// ---------------------------------------------------------------------------
// Prep: Pa[n][j] = sum_{k<64} x[n][k] * W1[k][j]
//       Pb[n][j] = sum_{k<64} x[n][k] * W1[64+k][j]
// block = 128 threads (thread = hidden unit j), 16 nodes per block.
// ---------------------------------------------------------------------------
__global__ void __launch_bounds__(128)
prep_nodes_kernel(const float* __restrict__ x, const float* __restrict__ W1)
{
    __shared__ float xs[NODE_DIM * 18];   // [k][n], stride 18 (rows 8B-aligned)
    const int t  = threadIdx.x;
    const int nb = blockIdx.x * 16;

    #pragma unroll
    for (int r = 0; r < 2; r++) {
        int u = t + r * 128;           // 0..255
        int n  = u >> 4;               // 0..15
        int kc = u & 15;               // float4 chunk
        float4 v = *(const float4*)(x + (size_t)(nb + n) * NODE_DIM + kc * 4);
        xs[(kc * 4 + 0) * 18 + n] = v.x;
        xs[(kc * 4 + 1) * 18 + n] = v.y;
        xs[(kc * 4 + 2) * 18 + n] = v.z;
        xs[(kc * 4 + 3) * 18 + n] = v.w;
    }
    __syncthreads();

    ull accA[8], accB[8];
    #pragma unroll
    for (int u = 0; u < 8; u++) { accA[u] = 0ULL; accB[u] = 0ULL; }

    #pragma unroll 4
    for (int k = 0; k < 64; k++) {
        const ull wa = pack2(W1[k * HID + t]);
        const ull wb = pack2(W1[(64 + k) * HID + t]);
        const ull* m = (const ull*)&xs[k * 18];
        #pragma unroll
        for (int u = 0; u < 8; u++) {
            accA[u] = ffma2(m[u], wa, accA[u]);
            accB[u] = ffma2(m[u], wb, accB[u]);
        }
    }

    #pragma unroll
    for (int u = 0; u < 8; u++) {
        float lo, hi;
        unpack2(accA[u], lo, hi);
        g_Pa[(size_t)(nb + 2 * u) * HID + t]     = lo;
        g_Pa[(size_t)(nb + 2 * u + 1) * HID + t] = hi;
        unpack2(accB[u], lo, hi);
        g_Pb[(size_t)(nb + 2 * u) * HID + t]     = lo;
        g_Pb[(size_t)(nb + 2 * u + 1) * HID + t] = hi;
    }
}

// ---------------------------------------------------------------------------
// Main: 32 edges per 128-thread block.
//   phase B: hreg[j0..j0+3][8 edges] += ea @ W1c   (thread: jg=t>>2, eg=t&3)
//   epilogue: + Pa[src] + Pb[tgt] + b1, relu -> hbuf[j][e]
//   GEMM2:   out = hbuf @ W2 + b2                  (thread: ng=t&15, eg2=t>>4)
// ---------------------------------------------------------------------------
__global__ void __launch_bounds__(128, 6)
edge_main_kernel(const float* __restrict__ ea,
                 const float* __restrict__ W1,
                 const float* __restrict__ b1,
                 const float* __restrict__ W2,
                 const float* __restrict__ b2,
                 const int* __restrict__ eidx,
                 float* __restrict__ out)
{
    __shared__ float eat[EDGE_DIM * 34];   // [k][e], stride 34
    __shared__ float hbuf[HID * 34];       // [j][e], stride 34
    __shared__ int   sidx[TILE_E];
    __shared__ int   tidx[TILE_E];

    const int t = threadIdx.x;
    const long long ebase = (long long)blockIdx.x * TILE_E;

    // indices (int32, [2, E] row-major)
    if (t < 64) {
        int e   = t & 31;
        int row = t >> 5;
        int v = eidx[(long long)row * E_TOTAL + ebase + e];
        if (row == 0) sidx[e] = v; else tidx[e] = v;
    }

    // stage ea transposed: eat[k][e]
    #pragma unroll
    for (int r = 0; r < 2; r++) {
        int u  = t + r * 128;   // 0..255
        int e  = u >> 3;        // 0..31
        int kc = u & 7;         // float4 chunk of the 32-float row
        float4 v = *(const float4*)(ea + (ebase + e) * EDGE_DIM + kc * 4);
        eat[(kc * 4 + 0) * 34 + e] = v.x;
        eat[(kc * 4 + 1) * 34 + e] = v.y;
        eat[(kc * 4 + 2) * 34 + e] = v.z;
        eat[(kc * 4 + 3) * 34 + e] = v.w;
    }
    __syncthreads();

    // ---- phase B: ea @ W1c into registers ----
    const int jg = t >> 2;          // 0..31  -> j0 = jg*4
    const int eg = t & 3;           // 0..3   -> edges eg*8 .. eg*8+7
    const int j0 = jg * 4;
    const int e0 = eg * 8;

    ull acc[4][4];                  // [i = j offset][p = edge pair]
    #pragma unroll
    for (int i = 0; i < 4; i++)
        #pragma unroll
        for (int p = 0; p < 4; p++) acc[i][p] = 0ULL;

    const float* w1c = W1 + 128 * HID + j0;
    #pragma unroll 4
    for (int k = 0; k < EDGE_DIM; k++) {
        const float4 w = *(const float4*)(w1c + k * HID);   // L1-resident (16 KB)
        const ull* m = (const ull*)&eat[k * 34 + e0];
        const ull w0 = pack2(w.x), w1 = pack2(w.y), w2 = pack2(w.z), w3 = pack2(w.w);
        #pragma unroll
        for (int p = 0; p < 4; p++) {
            acc[0][p] = ffma2(m[p], w0, acc[0][p]);
            acc[1][p] = ffma2(m[p], w1, acc[1][p]);
            acc[2][p] = ffma2(m[p], w2, acc[2][p]);
            acc[3][p] = ffma2(m[p], w3, acc[3][p]);
        }
    }

    // ---- epilogue: + Pa[src] + Pb[tgt] + b1, relu, store to hbuf ----
    {
        const float4 b1v = *(const float4*)(b1 + j0);
        const float* b1s = (const float*)&b1v;
        #pragma unroll
        for (int p = 0; p < 4; p++) {
            const int el = e0 + 2 * p;
            const float4 a0 = *(const float4*)(g_Pa + (size_t)sidx[el] * HID + j0);
            const float4 c0 = *(const float4*)(g_Pb + (size_t)tidx[el] * HID + j0);
            const float4 a1 = *(const float4*)(g_Pa + (size_t)sidx[el + 1] * HID + j0);
            const float4 c1 = *(const float4*)(g_Pb + (size_t)tidx[el + 1] * HID + j0);
            const float* a0s = (const float*)&a0; const float* c0s = (const float*)&c0;
            const float* a1s = (const float*)&a1; const float* c1s = (const float*)&c1;
            #pragma unroll
            for (int i = 0; i < 4; i++) {
                float lo, hi;
                unpack2(acc[i][p], lo, hi);
                lo = fmaxf(lo + a0s[i] + c0s[i] + b1s[i], 0.0f);
                hi = fmaxf(hi + a1s[i] + c1s[i] + b1s[i], 0.0f);
                *(ull*)&hbuf[(j0 + i) * 34 + el] = pack2f(lo, hi);
            }
        }
    }
    __syncthreads();

    // ---- GEMM2: out[e][n] = b2[n] + sum_j hbuf[j][e] * W2[j][n] ----
    {
        const int ng  = t & 15;      // n0 = ng*4
        const int eg2 = t >> 4;      // edges eg2*4 .. eg2*4+3 (2 pairs)
        const int n0  = ng * 4;
        const int ee0 = eg2 * 4;

        ull acc2[4][2];
        {
            const float4 b2v = *(const float4*)(b2 + n0);
            const float* b2s = (const float*)&b2v;
            #pragma unroll
            for (int i = 0; i < 4; i++) {
                const ull bi = pack2(b2s[i]);
                acc2[i][0] = bi; acc2[i][1] = bi;
            }
        }

        const float* w2p = W2 + n0;
        #pragma unroll 8
        for (int j = 0; j < HID; j++) {
            const float4 w = *(const float4*)(w2p + j * OUTD);  // L1-resident (32 KB)
            const ull* m = (const ull*)&hbuf[j * 34 + ee0];
            const ull m0 = m[0], m1 = m[1];
            const ull w0 = pack2(w.x), w1 = pack2(w.y), w2_ = pack2(w.z), w3 = pack2(w.w);
            acc2[0][0] = ffma2(m0, w0, acc2[0][0]);  acc2[0][1] = ffma2(m1, w0, acc2[0][1]);
            acc2[1][0] = ffma2(m0, w1, acc2[1][0]);  acc2[1][1] = ffma2(m1, w1, acc2[1][1]);
            acc2[2][0] = ffma2(m0, w2_, acc2[2][0]); acc2[2][1] = ffma2(m1, w2_, acc2[2][1]);
            acc2[3][0] = ffma2(m0, w3, acc2[3][0]);  acc2[3][1] = ffma2(m1, w3, acc2[3][1]);
        }

        #pragma unroll
        for (int u = 0; u < 2; u++) {
            float lo0, hi0, lo1, hi1, lo2, hi2, lo3, hi3;
            unpack2(acc2[0][u], lo0, hi0);
            unpack2(acc2[1][u], lo1, hi1);
            unpack2(acc2[2][u], lo2, hi2);
            unpack2(acc2[3][u], lo3, hi3);
            float4 v0 = make_float4(lo0, lo1, lo2, lo3);
            float4 v1 = make_float4(hi0, hi1, hi2, hi3);
            *(float4*)(out + (ebase + ee0 + 2 * u) * OUTD + n0)     = v0;
            *(float4*)(out + (ebase + ee0 + 2 * u + 1) * OUTD + n0) = v1;
        }
    }
}

extern "C" void kernel_launch(void* const* d_in, const int* in_sizes, int n_in,
                              void* d_out, int out_size) {
    const float* x   = (const float*)d_in[0];
    const float* ea  = (const float*)d_in[1];
    const float* W1  = (const float*)d_in[2];
    const float* b1  = (const float*)d_in[3];
    const float* W2  = (const float*)d_in[4];
    const float* b2  = (const float*)d_in[5];
    const int*   ei  = (const int*)d_in[6];
    float*       out = (float*)d_out;

    prep_nodes_kernel<<<N_NODES / 16, 128>>>(x, W1);            // 6250 blocks
    edge_main_kernel<<<E_TOTAL / TILE_E, 128>>>(ea, W1, b1, W2, b2, ei, out);  // 50000 blocks
}